// round 8
// baseline (speedup 1.0000x reference)
#include <cuda_runtime.h>
#include <cstdint>

// GroupFC: h[B,G,D], W[G,D,K], out[B,G,K] with L2-normalization on D for both.
#define B_SZ 256
#define G_SZ 100
#define D_SZ 768
#define K_SZ 128

#define BM 64
#define BN 128
#define BK 32
#define NTILE (D_SZ / BK)            // 24
#define A_STRIDE 36                  // 32+4 pad: conflict-free fragment LDS
#define B_STRIDE 136                 // 128+8 pad: conflict-free fragment LDS
#define SA_STAGE (BM * A_STRIDE)     // 2304 floats
#define SB_STAGE (BK * B_STRIDE)     // 4352 floats
#define SMEM_FLOATS (2 * SA_STAGE + 2 * SB_STAGE + BM + BN)   // 13504
#define SMEM_BYTES (SMEM_FLOATS * 4)                          // 54016

__device__ __forceinline__ uint32_t f2tf32(float f) {
    uint32_t u;
    asm("cvt.rna.tf32.f32 %0, %1;" : "=r"(u) : "f"(f));
    return u;
}

__device__ __forceinline__ void cp16(uint32_t saddr, const float* gaddr) {
    asm volatile("cp.async.cg.shared.global [%0], [%1], 16;"
                 :: "r"(saddr), "l"(gaddr));
}

__global__ __launch_bounds__(256, 2)
void groupfc_fused(const float* __restrict__ h,
                   const float* __restrict__ w,
                   float* __restrict__ out) {
    extern __shared__ float smem[];
    float* sA    = smem;                     // 2 stages of [BM][A_STRIDE], tf32 bits
    float* sB    = smem + 2 * SA_STAGE;      // 2 stages of [BK][B_STRIDE], raw fp32
    float* hsumS = sB + 2 * SB_STAGE;        // [BM]  sum of h^2 per local row
    float* wsumS = hsumS + BM;               // [BN]  sum of w^2 per column

    const int g    = blockIdx.y;
    const int m0   = blockIdx.x * BM;
    const int tid  = threadIdx.x;
    const int lane = tid & 31;
    const int warp = tid >> 5;
    const int gid  = lane >> 2;              // 0..7
    const int tig  = lane & 3;               // 0..3
    const int wm   = warp >> 2;              // 0..1 (m half: rows wm*32..+32)
    const int wn   = warp & 3;               // 0..3 (n quarter: cols wn*32..+32)

    const float* hbase = h + ((size_t)m0 * G_SZ + (size_t)g) * D_SZ;
    const float* wgrp  = w + (size_t)g * D_SZ * K_SZ;
    const size_t hstride = (size_t)G_SZ * D_SZ;   // between consecutive b rows

    const int arow = tid >> 3;               // 0..31 (A rows: arow, arow+32)
    const int ac4  = tid & 7;                // A col group of 4
    const int brow = tid >> 5;               // 0..7  (B rows: brow + 8j)
    const int bc4  = tid & 31;               // B col group of 4

    const uint32_t sB_base = (uint32_t)__cvta_generic_to_shared(sB);

    float acc[2][4][4];
#pragma unroll
    for (int mf = 0; mf < 2; mf++)
#pragma unroll
        for (int nf = 0; nf < 4; nf++)
#pragma unroll
            for (int q = 0; q < 4; q++) acc[mf][nf][q] = 0.f;

    float asq[2] = {0.f, 0.f};
    float wsq[4] = {0.f, 0.f, 0.f, 0.f};
    float4 rA[2];

    // ---- helpers ----
    auto ldgA = [&](int t) {                 // gmem -> regs, fused sum-of-squares
#pragma unroll
        for (int j = 0; j < 2; j++) {
            rA[j] = *reinterpret_cast<const float4*>(
                hbase + (size_t)(arow + j * 32) * hstride + t * BK + ac4 * 4);
            asq[j] = fmaf(rA[j].x, rA[j].x,
                     fmaf(rA[j].y, rA[j].y,
                     fmaf(rA[j].z, rA[j].z,
                     fmaf(rA[j].w, rA[j].w, asq[j]))));
        }
    };
    auto stsA = [&](int s) {                 // regs -> smem, converted to tf32
        float* dst = sA + s * SA_STAGE;
#pragma unroll
        for (int j = 0; j < 2; j++) {
            uint4 u;
            u.x = f2tf32(rA[j].x); u.y = f2tf32(rA[j].y);
            u.z = f2tf32(rA[j].z); u.w = f2tf32(rA[j].w);
            *reinterpret_cast<uint4*>(dst + (arow + j * 32) * A_STRIDE + ac4 * 4) = u;
        }
    };
    auto cpB = [&](int t, int s) {           // gmem -> smem via cp.async
        uint32_t dst = sB_base + (uint32_t)(s * SB_STAGE) * 4u;
#pragma unroll
        for (int j = 0; j < 4; j++) {
            int row = brow + j * 8;
            cp16(dst + (uint32_t)(row * B_STRIDE + bc4 * 4) * 4u,
                 wgrp + (size_t)(t * BK + row) * K_SZ + bc4 * 4);
        }
        asm volatile("cp.async.commit_group;");
    };
    auto compute = [&](int s) {
        const float* cA = sA + s * SA_STAGE;
        const float* cB = sB + s * SB_STAGE;
#pragma unroll
        for (int kk = 0; kk < BK; kk += 8) {
            uint32_t af[2][4], bf[4][2];
#pragma unroll
            for (int mf = 0; mf < 2; mf++) {
                const float* p = cA + (wm * 32 + mf * 16 + gid) * A_STRIDE + kk + tig;
                af[mf][0] = __float_as_uint(p[0]);
                af[mf][1] = __float_as_uint(p[8 * A_STRIDE]);
                af[mf][2] = __float_as_uint(p[4]);
                af[mf][3] = __float_as_uint(p[8 * A_STRIDE + 4]);
            }
#pragma unroll
            for (int nf = 0; nf < 4; nf++) {
                int cb = wn * 32 + nf * 8 + gid;
                bf[nf][0] = __float_as_uint(cB[(kk + tig) * B_STRIDE + cb]);
                bf[nf][1] = __float_as_uint(cB[(kk + tig + 4) * B_STRIDE + cb]);
            }
            if (wm == 0) {                   // warps 0..3 see each B element once
#pragma unroll
                for (int nf = 0; nf < 4; nf++) {
                    float b0 = __uint_as_float(bf[nf][0]);
                    float b1 = __uint_as_float(bf[nf][1]);
                    wsq[nf] = fmaf(b0, b0, fmaf(b1, b1, wsq[nf]));
                }
            }
#pragma unroll
            for (int mf = 0; mf < 2; mf++)
#pragma unroll
                for (int nf = 0; nf < 4; nf++) {
                    asm volatile(
                        "mma.sync.aligned.m16n8k8.row.col.f32.tf32.tf32.f32 "
                        "{%0,%1,%2,%3}, {%4,%5,%6,%7}, {%8,%9}, {%0,%1,%2,%3};"
                        : "+f"(acc[mf][nf][0]), "+f"(acc[mf][nf][1]),
                          "+f"(acc[mf][nf][2]), "+f"(acc[mf][nf][3])
                        : "r"(af[mf][0]), "r"(af[mf][1]),
                          "r"(af[mf][2]), "r"(af[mf][3]),
                          "r"(bf[nf][0]), "r"(bf[nf][1]));
                }
        }
    };

    // ---- prologue: stage tile 0 ----
    cpB(0, 0);
    ldgA(0);
    stsA(0);

    // ---- pipelined mainloop: one __syncthreads per tile ----
    int cur = 0;
    for (int t = 0; t < NTILE; t++) {
        int nxt = cur ^ 1;
        if (t + 1 < NTILE) {
            cpB(t + 1, nxt);
            ldgA(t + 1);
            asm volatile("cp.async.wait_group 1;");
        } else {
            asm volatile("cp.async.wait_group 0;");
        }
        __syncthreads();
        compute(cur);
        if (t + 1 < NTILE) stsA(nxt);
        cur = nxt;
    }

    // ---- norm reductions ----
#pragma unroll
    for (int j = 0; j < 2; j++) {            // 8 lanes (same lane>>3) share a row
        float s = asq[j];
        s += __shfl_xor_sync(0xffffffffu, s, 1);
        s += __shfl_xor_sync(0xffffffffu, s, 2);
        s += __shfl_xor_sync(0xffffffffu, s, 4);
        if ((lane & 7) == 0) hsumS[arow + j * 32] = s;
    }
    if (wm == 0) {                           // 4 tig lanes share each w column
#pragma unroll
        for (int nf = 0; nf < 4; nf++) {
            float s = wsq[nf];
            s += __shfl_xor_sync(0xffffffffu, s, 1);
            s += __shfl_xor_sync(0xffffffffu, s, 2);
            if (tig == 0) wsumS[wn * 32 + nf * 8 + gid] = s;
        }
    }
    __syncthreads();

    // ---- epilogue: scale by 1/(||h_row|| * ||w_col||), store ----
    float rwv[4][2];
#pragma unroll
    for (int nf = 0; nf < 4; nf++) {
        int c = wn * 32 + nf * 8 + tig * 2;
        rwv[nf][0] = 1.0f / fmaxf(sqrtf(wsumS[c]), 1e-12f);
        rwv[nf][1] = 1.0f / fmaxf(sqrtf(wsumS[c + 1]), 1e-12f);
    }
#pragma unroll
    for (int mf = 0; mf < 2; mf++) {
        int r  = wm * 32 + mf * 16 + gid;
        int b0 = m0 + r;
        float rh0 = 1.0f / fmaxf(sqrtf(hsumS[r]), 1e-12f);
        float rh1 = 1.0f / fmaxf(sqrtf(hsumS[r + 8]), 1e-12f);
        float* o0 = out + ((size_t)b0 * G_SZ + g) * K_SZ;
        float* o1 = o0 + (size_t)8 * G_SZ * K_SZ;
#pragma unroll
        for (int nf = 0; nf < 4; nf++) {
            int c = wn * 32 + nf * 8 + tig * 2;
            float2 v0 = make_float2(acc[mf][nf][0] * rh0 * rwv[nf][0],
                                    acc[mf][nf][1] * rh0 * rwv[nf][1]);
            float2 v1 = make_float2(acc[mf][nf][2] * rh1 * rwv[nf][0],
                                    acc[mf][nf][3] * rh1 * rwv[nf][1]);
            *reinterpret_cast<float2*>(o0 + c) = v0;
            *reinterpret_cast<float2*>(o1 + c) = v1;
        }
    }
}

extern "C" void kernel_launch(void* const* d_in, const int* in_sizes, int n_in,
                              void* d_out, int out_size) {
    const float* h = (const float*)d_in[0];   // [B,G,D]
    const float* w = (const float*)d_in[1];   // [G,D,K]
    float* out     = (float*)d_out;           // [B,G,K]
    (void)in_sizes; (void)n_in; (void)out_size;

    cudaFuncSetAttribute(groupfc_fused,
                         cudaFuncAttributeMaxDynamicSharedMemorySize, SMEM_BYTES);
    groupfc_fused<<<dim3(B_SZ / BM, G_SZ), 256, SMEM_BYTES>>>(h, w, out);
}

// round 9
// speedup vs baseline: 1.3810x; 1.3810x over previous
#include <cuda_runtime.h>
#include <cstdint>

// GroupFC: h[B,G,D], W[G,D,K], out[B,G,K] with L2-normalization on D for both.
#define B_SZ 256
#define G_SZ 100
#define D_SZ 768
#define K_SZ 128

#define BM 64
#define BN 128
#define BK 32
#define NTILE (D_SZ / BK)            // 24
#define A_STRIDE 36                  // 32+4 pad: conflict-free fragment LDS
#define B_STRIDE 136                 // 128+8 pad: conflict-free fragment LDS
#define SA_STAGE (BM * A_STRIDE)     // 2304 floats
#define SB_STAGE (BK * B_STRIDE)     // 4352 floats
#define SMEM_FLOATS (2 * SA_STAGE + 2 * SB_STAGE + BM + BN)   // 13504
#define SMEM_BYTES (SMEM_FLOATS * 4)                          // 54016

__device__ __forceinline__ uint32_t f2tf32(float f) {
    uint32_t u;
    asm("cvt.rna.tf32.f32 %0, %1;" : "=r"(u) : "f"(f));
    return u;
}

__device__ __forceinline__ void cp16(uint32_t saddr, const float* gaddr) {
    asm volatile("cp.async.cg.shared.global [%0], [%1], 16;"
                 :: "r"(saddr), "l"(gaddr));
}

// occ=3 is the load-bearing change: 400 CTAs all resident in ONE wave
// (444 slots), 21.6 warps/SM avg, no wave-quantization tail.
__global__ __launch_bounds__(256, 3)
void groupfc_fused(const float* __restrict__ h,
                   const float* __restrict__ w,
                   float* __restrict__ out) {
    extern __shared__ float smem[];
    float* sA    = smem;                     // 2 stages of [BM][A_STRIDE], tf32 bits
    float* sB    = smem + 2 * SA_STAGE;      // 2 stages of [BK][B_STRIDE], raw fp32
    float* hsumS = sB + 2 * SB_STAGE;        // [BM]  sum of h^2 per local row
    float* wsumS = hsumS + BM;               // [BN]  sum of w^2 per column

    const int g    = blockIdx.y;
    const int m0   = blockIdx.x * BM;
    const int tid  = threadIdx.x;
    const int lane = tid & 31;
    const int warp = tid >> 5;
    const int gid  = lane >> 2;              // 0..7
    const int tig  = lane & 3;               // 0..3
    const int wm   = warp >> 2;              // 0..1 (m half: rows wm*32..+32)
    const int wn   = warp & 3;               // 0..3 (n quarter: cols wn*32..+32)

    const float* hbase = h + ((size_t)m0 * G_SZ + (size_t)g) * D_SZ;
    const float* wgrp  = w + (size_t)g * D_SZ * K_SZ;
    const size_t hstride = (size_t)G_SZ * D_SZ;   // between consecutive b rows

    const int arow = tid >> 3;               // 0..31 (A rows: arow, arow+32)
    const int ac4  = tid & 7;                // A col group of 4
    const int brow = tid >> 5;               // 0..7  (B rows: brow + 8j)
    const int bc4  = tid & 31;               // B col group of 4

    const uint32_t sB_base = (uint32_t)__cvta_generic_to_shared(sB);

    float acc[2][4][4];
#pragma unroll
    for (int mf = 0; mf < 2; mf++)
#pragma unroll
        for (int nf = 0; nf < 4; nf++)
#pragma unroll
            for (int q = 0; q < 4; q++) acc[mf][nf][q] = 0.f;

    float asq[2] = {0.f, 0.f};
    float wsq[4] = {0.f, 0.f, 0.f, 0.f};
    float4 rA[2];

    // ---- helpers ----
    auto ldgA = [&](int t) {                 // gmem -> regs, fused sum-of-squares
#pragma unroll
        for (int j = 0; j < 2; j++) {
            rA[j] = *reinterpret_cast<const float4*>(
                hbase + (size_t)(arow + j * 32) * hstride + t * BK + ac4 * 4);
            asq[j] = fmaf(rA[j].x, rA[j].x,
                     fmaf(rA[j].y, rA[j].y,
                     fmaf(rA[j].z, rA[j].z,
                     fmaf(rA[j].w, rA[j].w, asq[j]))));
        }
    };
    auto stsA = [&](int s) {                 // regs -> smem, converted to tf32
        float* dst = sA + s * SA_STAGE;
#pragma unroll
        for (int j = 0; j < 2; j++) {
            uint4 u;
            u.x = f2tf32(rA[j].x); u.y = f2tf32(rA[j].y);
            u.z = f2tf32(rA[j].z); u.w = f2tf32(rA[j].w);
            *reinterpret_cast<uint4*>(dst + (arow + j * 32) * A_STRIDE + ac4 * 4) = u;
        }
    };
    auto cpB = [&](int t, int s) {           // gmem -> smem via cp.async
        uint32_t dst = sB_base + (uint32_t)(s * SB_STAGE) * 4u;
#pragma unroll
        for (int j = 0; j < 4; j++) {
            int row = brow + j * 8;
            cp16(dst + (uint32_t)(row * B_STRIDE + bc4 * 4) * 4u,
                 wgrp + (size_t)(t * BK + row) * K_SZ + bc4 * 4);
        }
        asm volatile("cp.async.commit_group;");
    };
    auto compute = [&](int s) {
        const float* cA = sA + s * SA_STAGE;
        const float* cB = sB + s * SB_STAGE;
#pragma unroll
        for (int kk = 0; kk < BK; kk += 8) {
            uint32_t af[2][4], bf[4][2];
#pragma unroll
            for (int mf = 0; mf < 2; mf++) {
                const float* p = cA + (wm * 32 + mf * 16 + gid) * A_STRIDE + kk + tig;
                af[mf][0] = __float_as_uint(p[0]);
                af[mf][1] = __float_as_uint(p[8 * A_STRIDE]);
                af[mf][2] = __float_as_uint(p[4]);
                af[mf][3] = __float_as_uint(p[8 * A_STRIDE + 4]);
            }
#pragma unroll
            for (int nf = 0; nf < 4; nf++) {
                int cb = wn * 32 + nf * 8 + gid;
                bf[nf][0] = __float_as_uint(cB[(kk + tig) * B_STRIDE + cb]);
                bf[nf][1] = __float_as_uint(cB[(kk + tig + 4) * B_STRIDE + cb]);
            }
            if (wm == 0) {                   // warps 0..3 see each B element once
#pragma unroll
                for (int nf = 0; nf < 4; nf++) {
                    float b0 = __uint_as_float(bf[nf][0]);
                    float b1 = __uint_as_float(bf[nf][1]);
                    wsq[nf] = fmaf(b0, b0, fmaf(b1, b1, wsq[nf]));
                }
            }
#pragma unroll
            for (int mf = 0; mf < 2; mf++)
#pragma unroll
                for (int nf = 0; nf < 4; nf++) {
                    asm volatile(
                        "mma.sync.aligned.m16n8k8.row.col.f32.tf32.tf32.f32 "
                        "{%0,%1,%2,%3}, {%4,%5,%6,%7}, {%8,%9}, {%0,%1,%2,%3};"
                        : "+f"(acc[mf][nf][0]), "+f"(acc[mf][nf][1]),
                          "+f"(acc[mf][nf][2]), "+f"(acc[mf][nf][3])
                        : "r"(af[mf][0]), "r"(af[mf][1]),
                          "r"(af[mf][2]), "r"(af[mf][3]),
                          "r"(bf[nf][0]), "r"(bf[nf][1]));
                }
        }
    };

    // ---- prologue: stage tile 0 ----
    cpB(0, 0);
    ldgA(0);
    stsA(0);

    // ---- pipelined mainloop: one __syncthreads per tile ----
    int cur = 0;
    for (int t = 0; t < NTILE; t++) {
        int nxt = cur ^ 1;
        if (t + 1 < NTILE) {
            cpB(t + 1, nxt);
            ldgA(t + 1);
            asm volatile("cp.async.wait_group 1;");
        } else {
            asm volatile("cp.async.wait_group 0;");
        }
        __syncthreads();
        compute(cur);
        if (t + 1 < NTILE) stsA(nxt);
        cur = nxt;
    }

    // ---- norm reductions ----
#pragma unroll
    for (int j = 0; j < 2; j++) {            // 8 lanes (same lane>>3) share a row
        float s = asq[j];
        s += __shfl_xor_sync(0xffffffffu, s, 1);
        s += __shfl_xor_sync(0xffffffffu, s, 2);
        s += __shfl_xor_sync(0xffffffffu, s, 4);
        if ((lane & 7) == 0) hsumS[arow + j * 32] = s;
    }
    if (wm == 0) {                           // 4 tig lanes share each w column
#pragma unroll
        for (int nf = 0; nf < 4; nf++) {
            float s = wsq[nf];
            s += __shfl_xor_sync(0xffffffffu, s, 1);
            s += __shfl_xor_sync(0xffffffffu, s, 2);
            if (tig == 0) wsumS[wn * 32 + nf * 8 + gid] = s;
        }
    }
    __syncthreads();

    // ---- epilogue: scale by 1/(||h_row|| * ||w_col||), store ----
#pragma unroll
    for (int mf = 0; mf < 2; mf++) {
        int r  = wm * 32 + mf * 16 + gid;
        int b0 = m0 + r;
        float rh0 = 1.0f / fmaxf(sqrtf(hsumS[r]), 1e-12f);
        float rh1 = 1.0f / fmaxf(sqrtf(hsumS[r + 8]), 1e-12f);
        float* o0 = out + ((size_t)b0 * G_SZ + g) * K_SZ;
        float* o1 = o0 + (size_t)8 * G_SZ * K_SZ;
#pragma unroll
        for (int nf = 0; nf < 4; nf++) {
            int c = wn * 32 + nf * 8 + tig * 2;
            float rw0 = 1.0f / fmaxf(sqrtf(wsumS[c]), 1e-12f);
            float rw1 = 1.0f / fmaxf(sqrtf(wsumS[c + 1]), 1e-12f);
            float2 v0 = make_float2(acc[mf][nf][0] * rh0 * rw0,
                                    acc[mf][nf][1] * rh0 * rw1);
            float2 v1 = make_float2(acc[mf][nf][2] * rh1 * rw0,
                                    acc[mf][nf][3] * rh1 * rw1);
            *reinterpret_cast<float2*>(o0 + c) = v0;
            *reinterpret_cast<float2*>(o1 + c) = v1;
        }
    }
}

extern "C" void kernel_launch(void* const* d_in, const int* in_sizes, int n_in,
                              void* d_out, int out_size) {
    const float* h = (const float*)d_in[0];   // [B,G,D]
    const float* w = (const float*)d_in[1];   // [G,D,K]
    float* out     = (float*)d_out;           // [B,G,K]
    (void)in_sizes; (void)n_in; (void)out_size;

    cudaFuncSetAttribute(groupfc_fused,
                         cudaFuncAttributeMaxDynamicSharedMemorySize, SMEM_BYTES);
    groupfc_fused<<<dim3(B_SZ / BM, G_SZ), 256, SMEM_BYTES>>>(h, w, out);
}

// round 11
// speedup vs baseline: 1.5243x; 1.1038x over previous
#include <cuda_runtime.h>
#include <cuda_fp16.h>
#include <cstdint>

// GroupFC: h[B,G,D], W[G,D,K], out[B,G,K]; out = normalize(h) @ normalize_d(W)
#define B_SZ 256
#define G_SZ 100
#define D_SZ 768
#define K_SZ 128

#define BM 64
#define BN 128
#define BK 32
#define NTILE (D_SZ / BK)        // 24
#define SAU 20                   // uints per A row: 16 fp16x2 + 4 pad
#define SBU 136                  // uints per B d2-row: 128 + 8 pad
#define SA_ST (BM * SAU)         // 1280 uints / stage
#define SB_ST ((BK / 2) * SBU)   // 2176 uints / stage

// pack two floats to fp16x2 (lo = first element). PTX cvt.f16x2 packs src1->hi.
__device__ __forceinline__ uint32_t packh2(float lo, float hi) {
    uint32_t u;
    asm("cvt.rn.f16x2.f32 %0, %1, %2;" : "=r"(u) : "f"(hi), "f"(lo));
    return u;
}

__global__ __launch_bounds__(256, 3)
void groupfc_h2(const float* __restrict__ h,
                const float* __restrict__ w,
                float* __restrict__ out) {
    // static smem: 2*(1280+2176)*4 + 256 + 4096 + 512 = 32512 B
    __shared__ uint32_t uA[2 * SA_ST];     // A tiles, fp16x2 pairs along k
    __shared__ uint32_t uB[2 * SB_ST];     // B tiles, fp16x2 pairs along d, d2-major
    __shared__ float hsum[BM];             // raw sum h^2 per local row
    __shared__ float wpart[8 * BN];        // per-warp partial sum w^2 per col
    __shared__ float wsum[BN];             // raw sum w^2 per col

    const int g    = blockIdx.y;
    const int m0   = blockIdx.x * BM;
    const int tid  = threadIdx.x;
    const int lane = tid & 31;
    const int warp = tid >> 5;
    const int gid  = lane >> 2;            // 0..7
    const int tig  = lane & 3;             // 0..3
    const int wm   = warp >> 2;            // 0..1 : rows wm*32..+32
    const int wn   = warp & 3;             // 0..3 : cols wn*32..+32

    const float* hbase = h + ((size_t)m0 * G_SZ + (size_t)g) * D_SZ;
    const float* wgrp  = w + (size_t)g * D_SZ * K_SZ;
    const size_t hstride = (size_t)G_SZ * D_SZ;

    const int arow = tid >> 3;             // A rows {arow, arow+32}
    const int ac4  = tid & 7;              // A k-chunk of 4
    const int dp   = tid >> 4;             // B d-pair 0..15 (d = 2dp, 2dp+1)
    const int n8   = (tid & 15) * 8;       // B col chunk of 8

    float acc[2][4][4];
#pragma unroll
    for (int mf = 0; mf < 2; mf++)
#pragma unroll
        for (int nf = 0; nf < 4; nf++)
#pragma unroll
            for (int q = 0; q < 4; q++) acc[mf][nf][q] = 0.f;

    float asq[2] = {0.f, 0.f};
    float wsq[8] = {0, 0, 0, 0, 0, 0, 0, 0};
    float4 rA[2], rB0[2], rB1[2];

    auto ldg = [&](int t) {
#pragma unroll
        for (int j = 0; j < 2; j++)
            rA[j] = *reinterpret_cast<const float4*>(
                hbase + (size_t)(arow + 32 * j) * hstride + t * BK + ac4 * 4);
        const float* wb = wgrp + (size_t)(t * BK + 2 * dp) * K_SZ + n8;
        rB0[0] = *reinterpret_cast<const float4*>(wb);
        rB0[1] = *reinterpret_cast<const float4*>(wb + 4);
        rB1[0] = *reinterpret_cast<const float4*>(wb + K_SZ);
        rB1[1] = *reinterpret_cast<const float4*>(wb + K_SZ + 4);
    };
    auto sts = [&](int s) {
        // A: fuse h sum-of-squares (exact fp32), convert, st.v2
        uint32_t* da = uA + s * SA_ST;
#pragma unroll
        for (int j = 0; j < 2; j++) {
            float4 v = rA[j];
            asq[j] = fmaf(v.x, v.x, fmaf(v.y, v.y,
                     fmaf(v.z, v.z, fmaf(v.w, v.w, asq[j]))));
            uint2 u = make_uint2(packh2(v.x, v.y), packh2(v.z, v.w));
            *reinterpret_cast<uint2*>(da + (arow + 32 * j) * SAU + ac4 * 2) = u;
        }
        // B: pack (d, d+1) pairs per col, fuse w sum-of-squares, st.v4
        uint32_t* db = uB + s * SB_ST + dp * SBU + n8;
#pragma unroll
        for (int q = 0; q < 2; q++) {
            float4 lo = rB0[q], hi = rB1[q];
            wsq[q * 4 + 0] = fmaf(lo.x, lo.x, fmaf(hi.x, hi.x, wsq[q * 4 + 0]));
            wsq[q * 4 + 1] = fmaf(lo.y, lo.y, fmaf(hi.y, hi.y, wsq[q * 4 + 1]));
            wsq[q * 4 + 2] = fmaf(lo.z, lo.z, fmaf(hi.z, hi.z, wsq[q * 4 + 2]));
            wsq[q * 4 + 3] = fmaf(lo.w, lo.w, fmaf(hi.w, hi.w, wsq[q * 4 + 3]));
            uint4 u = make_uint4(packh2(lo.x, hi.x), packh2(lo.y, hi.y),
                                 packh2(lo.z, hi.z), packh2(lo.w, hi.w));
            *reinterpret_cast<uint4*>(db + q * 4) = u;
        }
    };
    auto compute = [&](int s) {
        const uint32_t* cA = uA + s * SA_ST;
        const uint32_t* cB = uB + s * SB_ST;
#pragma unroll
        for (int ks = 0; ks < 2; ks++) {           // two k16 steps per BK=32
            const int kb = ks * 8;
            uint32_t af[2][4], bf[4][2];
#pragma unroll
            for (int mf = 0; mf < 2; mf++) {
                const uint32_t* p = cA + (wm * 32 + mf * 16 + gid) * SAU + kb + tig;
                af[mf][0] = p[0];
                af[mf][1] = p[8 * SAU];
                af[mf][2] = p[4];
                af[mf][3] = p[8 * SAU + 4];
            }
#pragma unroll
            for (int nf = 0; nf < 4; nf++) {
                const int cb = wn * 32 + nf * 8 + gid;
                bf[nf][0] = cB[(kb + tig) * SBU + cb];
                bf[nf][1] = cB[(kb + tig + 4) * SBU + cb];
            }
#pragma unroll
            for (int mf = 0; mf < 2; mf++)
#pragma unroll
                for (int nf = 0; nf < 4; nf++) {
                    asm volatile(
                        "mma.sync.aligned.m16n8k16.row.col.f32.f16.f16.f32 "
                        "{%0,%1,%2,%3}, {%4,%5,%6,%7}, {%8,%9}, {%0,%1,%2,%3};"
                        : "+f"(acc[mf][nf][0]), "+f"(acc[mf][nf][1]),
                          "+f"(acc[mf][nf][2]), "+f"(acc[mf][nf][3])
                        : "r"(af[mf][0]), "r"(af[mf][1]),
                          "r"(af[mf][2]), "r"(af[mf][3]),
                          "r"(bf[nf][0]), "r"(bf[nf][1]));
                }
        }
    };

    // ---- pipeline: ldg(t+1) | compute(t) | sts(t+1), one barrier/tile ----
    ldg(0); sts(0);
    __syncthreads();
    for (int t = 0; t < NTILE; t++) {
        const int cur = t & 1;
        if (t + 1 < NTILE) ldg(t + 1);
        compute(cur);
        if (t + 1 < NTILE) sts(cur ^ 1);
        __syncthreads();
    }

    // ---- norm reductions (raw sums; rsqrt applied inline in epilogue) ----
#pragma unroll
    for (int j = 0; j < 2; j++) {          // 8 lanes share each h row
        float s = asq[j];
        s += __shfl_xor_sync(0xffffffffu, s, 1);
        s += __shfl_xor_sync(0xffffffffu, s, 2);
        s += __shfl_xor_sync(0xffffffffu, s, 4);
        if ((lane & 7) == 0) hsum[arow + 32 * j] = s;
    }
    {
        // threads sharing a column: same (tid&15) -> lane, lane+16 across warps
#pragma unroll
        for (int c = 0; c < 8; c++)
            wsq[c] += __shfl_xor_sync(0xffffffffu, wsq[c], 16);
        if (lane < 16) {
#pragma unroll
            for (int c = 0; c < 8; c++)
                wpart[warp * BN + (lane & 15) * 8 + c] = wsq[c];
        }
    }
    __syncthreads();
    if (tid < BN) {
        float s = 0.f;
#pragma unroll
        for (int wp = 0; wp < 8; wp++) s += wpart[wp * BN + tid];
        wsum[tid] = s;
    }
    __syncthreads();

    // ---- epilogue: scale by 1/(||h_row||*||w_col||), store ----
#pragma unroll
    for (int mf = 0; mf < 2; mf++) {
        int r  = wm * 32 + mf * 16 + gid;
        int b0 = m0 + r;
        float rh0 = 1.0f / fmaxf(sqrtf(hsum[r]), 1e-12f);
        float rh1 = 1.0f / fmaxf(sqrtf(hsum[r + 8]), 1e-12f);
        float* o0 = out + ((size_t)b0 * G_SZ + g) * K_SZ;
        float* o1 = o0 + (size_t)8 * G_SZ * K_SZ;
#pragma unroll
        for (int nf = 0; nf < 4; nf++) {
            int c = wn * 32 + nf * 8 + tig * 2;
            float rw0 = 1.0f / fmaxf(sqrtf(wsum[c]), 1e-12f);
            float rw1 = 1.0f / fmaxf(sqrtf(wsum[c + 1]), 1e-12f);
            float2 v0 = make_float2(acc[mf][nf][0] * rh0 * rw0,
                                    acc[mf][nf][1] * rh0 * rw1);
            float2 v1 = make_float2(acc[mf][nf][2] * rh1 * rw0,
                                    acc[mf][nf][3] * rh1 * rw1);
            *reinterpret_cast<float2*>(o0 + c) = v0;
            *reinterpret_cast<float2*>(o1 + c) = v1;
        }
    }
}

extern "C" void kernel_launch(void* const* d_in, const int* in_sizes, int n_in,
                              void* d_out, int out_size) {
    const float* h = (const float*)d_in[0];   // [B,G,D]
    const float* w = (const float*)d_in[1];   // [G,D,K]
    float* out     = (float*)d_out;           // [B,G,K]
    (void)in_sizes; (void)n_in; (void)out_size;

    groupfc_h2<<<dim3(B_SZ / BM, G_SZ), 256>>>(h, w, out);
}